// round 10
// baseline (speedup 1.0000x reference)
#include <cuda_runtime.h>
#include <stdint.h>

#define N_POINTS 1200000
#define NFEAT 5
#define GXD 400
#define GYD 400
#define NCELLS (GXD*GYD)          // 160000
#define NCELLS_PAD 163840         // 40 * 4096
#define MAXV 60000
#define MAXP 32
#define OUT_COORD_OFF (MAXV*MAXP*NFEAT)        // 9,600,000
#define OUT_NUM_OFF   (OUT_COORD_OFF + MAXV*3) // 9,780,000
#define SCAN_BLOCKS 40
#define CELLS_PER_BLOCK 4096       // 1024 threads * 4 cells
#define DYN_TOTAL (NCELLS_PAD + SCAN_BLOCKS)
#define PPT 8                      // points per thread in assign

// [0,NCELLS_PAD) = per-cell counts, then SCAN_BLOCKS lookback states.
// Zero-initialized at load; k_emit re-zeroes it each launch for the next replay.
__device__ unsigned g_dyn[DYN_TOTAL];
__device__ int      g_totvox;
__device__ unsigned g_voxlist[MAXV];            // cell(18b) | min(cnt,16383)<<18
// slot[cell][rank] = {x,y,z,idx_bits},{f3,f4,-,-}: 32B per point, 32B-aligned (one sector)
__device__ float4   g_slot[(size_t)NCELLS * MAXP * 2];

__device__ __forceinline__ void do_point(int idx, float x, float y, float z,
                                         float f3, float f4) {
    // exact: (v+50)*4 == (v-(-50))/0.25 ; (v+5)*0.125 == (v-(-5))/8
    int cx = (int)floorf((x + 50.0f) * 4.0f);
    int cy = (int)floorf((y + 50.0f) * 4.0f);
    int cz = (int)floorf((z + 5.0f) * 0.125f);
    if (cx >= 0 && cx < GXD && cy >= 0 && cy < GYD && cz == 0) {
        int cell = cy * GXD + cx;
        unsigned r = atomicAdd(&g_dyn[cell], 1u);
        if (r < MAXP) {
            size_t s = ((size_t)cell * MAXP + r) * 2;
            g_slot[s]     = make_float4(x, y, z, __int_as_float(idx));
            g_slot[s + 1] = make_float4(f3, f4, 0.0f, 0.0f);
        }
    }
}

// ---------------- assign: 8 points/thread, stage full point (same sectors as 4B) ----------------
__global__ void __launch_bounds__(256, 4) k_assign(const float4* __restrict__ pts4) {
    int t = blockIdx.x * blockDim.x + threadIdx.x;
    if (t >= N_POINTS / PPT) return;
    // 8 points = 160 bytes = 10 aligned float4 loads, all independent
    const float4* src = pts4 + (size_t)t * 10;
    float4 q0 = src[0], q1 = src[1], q2 = src[2], q3 = src[3], q4 = src[4];
    float4 q5 = src[5], q6 = src[6], q7 = src[7], q8 = src[8], q9 = src[9];
    int base = t * PPT;
    // point k = floats [5k,5k+5) across q0..q9 (static mapping, no local array)
    do_point(base + 0, q0.x, q0.y, q0.z, q0.w, q1.x);
    do_point(base + 1, q1.y, q1.z, q1.w, q2.x, q2.y);
    do_point(base + 2, q2.z, q2.w, q3.x, q3.y, q3.z);
    do_point(base + 3, q3.w, q4.x, q4.y, q4.z, q4.w);
    do_point(base + 4, q5.x, q5.y, q5.z, q5.w, q6.x);
    do_point(base + 5, q6.y, q6.z, q6.w, q7.x, q7.y);
    do_point(base + 6, q7.z, q7.w, q8.x, q8.y, q8.z);
    do_point(base + 7, q8.w, q9.x, q9.y, q9.z, q9.w);
}

// ---------------- scan: single-wave decoupled lookback + voxel-list compaction ----------------
__global__ void __launch_bounds__(1024, 1) k_scan() {
    __shared__ int wsum[32];
    __shared__ unsigned s_prefix;
    unsigned* state = g_dyn + NCELLS_PAD;
    const int t = threadIdx.x, b = blockIdx.x;
    const int lane = t & 31, w = t >> 5;
    const int c0 = b * CELLS_PER_BLOCK + t * 4;

    uint4 c4 = *(const uint4*)&g_dyn[c0];
    int o0 = c4.x ? 1 : 0, o1 = c4.y ? 1 : 0, o2 = c4.z ? 1 : 0, o3 = c4.w ? 1 : 0;
    int s = o0 + o1 + o2 + o3;

    int x = s;
    #pragma unroll
    for (int o = 1; o < 32; o <<= 1) {
        int v = __shfl_up_sync(0xffffffffu, x, o);
        if (lane >= o) x += v;
    }
    if (lane == 31) wsum[w] = x;
    __syncthreads();
    if (w == 0) {
        int y = wsum[lane];
        #pragma unroll
        for (int o = 1; o < 32; o <<= 1) {
            int v = __shfl_up_sync(0xffffffffu, y, o);
            if (lane >= o) y += v;
        }
        wsum[lane] = y;
    }
    __syncthreads();
    int incl = x + (w ? wsum[w - 1] : 0);
    unsigned agg = (unsigned)wsum[31];

    if (t == 0) {
        if (b == 0) atomicExch(&state[0], (2u << 30) | agg);
        else        atomicExch(&state[b], (1u << 30) | agg);
    }
    if (w == 0) {
        if (b == 0) { if (lane == 0) s_prefix = 0; }
        else {
            unsigned run = 0;
            int j = b - 1 - lane;
            for (;;) {
                unsigned sv = (j >= 0) ? *(volatile unsigned*)&state[j] : (2u << 30);
                unsigned flag = sv >> 30;
                if (__all_sync(0xffffffffu, flag != 0u)) {
                    unsigned pm = __ballot_sync(0xffffffffu, flag >= 2u);
                    int fp = (pm != 0u) ? (__ffs(pm) - 1) : -1;
                    unsigned contrib = (fp < 0 || lane <= fp) ? (sv & 0x3FFFFFFFu) : 0u;
                    #pragma unroll
                    for (int o = 16; o; o >>= 1)
                        contrib += __shfl_down_sync(0xffffffffu, contrib, o);
                    contrib = __shfl_sync(0xffffffffu, contrib, 0);
                    run += contrib;
                    if (fp >= 0) break;
                    j -= 32;
                }
            }
            if (lane == 0) {
                s_prefix = run;
                atomicExch(&state[b], (2u << 30) | (run + agg));
            }
        }
    }
    __syncthreads();

    int e = (int)s_prefix + incl - s;   // exclusive prefix of occupancy before cell c0
    if (o0) { if (e < MAXV) g_voxlist[e] = (unsigned)(c0+0) | (umin(c4.x, 16383u) << 18); e++; }
    if (o1) { if (e < MAXV) g_voxlist[e] = (unsigned)(c0+1) | (umin(c4.y, 16383u) << 18); e++; }
    if (o2) { if (e < MAXV) g_voxlist[e] = (unsigned)(c0+2) | (umin(c4.z, 16383u) << 18); e++; }
    if (o3) { if (e < MAXV) g_voxlist[e] = (unsigned)(c0+3) | (umin(c4.w, 16383u) << 18); e++; }
    if (b == SCAN_BLOCKS - 1 && t == 1023) g_totvox = e;
}

// ---------------- emit: one warp per OUTPUT voxel; coalesced slot read, no pts gather ----------------
__global__ void __launch_bounds__(256) k_emit(const float* __restrict__ pts,
                                              float* __restrict__ out) {
    int gid  = blockIdx.x * blockDim.x + threadIdx.x;
    int gw   = gid >> 5;                  // voxel index
    int lane = threadIdx.x & 31;
    int w    = (threadIdx.x >> 5) & 7;
    __shared__ float sbuf[8][160];
    __shared__ int   sidx[8][32];

    // reset counters + lookback state for the next replay (globals start zeroed at load)
    if (gid < DYN_TOTAL) g_dyn[gid] = 0;

    if (gw >= MAXV) return;
    int tv = g_totvox;
    if (gw >= tv) {
        // zero-fill unowned voxel (no-op when totvox >= MAXV)
        float4 z = make_float4(0.f, 0.f, 0.f, 0.f);
        float4* dst = (float4*)(out + (size_t)gw * (MAXP * NFEAT));
        for (int j = lane; j < 40; j += 32) __stcs(&dst[j], z);
        if (lane == 0) {
            float* oc = out + OUT_COORD_OFF + (size_t)gw * 3;
            __stcs(&oc[0], 0.f); __stcs(&oc[1], 0.f); __stcs(&oc[2], 0.f);
            __stcs(&out[OUT_NUM_OFF + gw], 0.f);
        }
        return;
    }

    unsigned packed = __ldcs(&g_voxlist[gw]);
    int cell = (int)(packed & 0x3FFFFu);
    int cnt  = (int)(packed >> 18);
    float f0 = 0.f, f1 = 0.f, f2 = 0.f, f3 = 0.f, f4 = 0.f;
    int slot, n;

    if (cnt <= MAXP) {
        n = cnt;
        int idx = 0x7fffffff;
        if (lane < cnt) {
            size_t s = ((size_t)cell * MAXP + lane) * 2;
            float4 a  = __ldcs(&g_slot[s]);       // coalesced: warp reads contiguous 32B/lane
            float4 bb = __ldcs(&g_slot[s + 1]);
            idx = __float_as_int(a.w);
            f0 = a.x; f1 = a.y; f2 = a.z; f3 = bb.x; f4 = bb.y;
        }
        int rank = 0;
        #pragma unroll
        for (int k = 0; k < 32; k++) {
            int o = __shfl_sync(0xffffffffu, idx, k);
            rank += (o < idx) ? 1 : 0;
        }
        slot = (lane < cnt) ? rank : lane;   // ranks tile [0,cnt), idle lanes tile [cnt,32)
        if (lane >= cnt) { f0 = f1 = f2 = f3 = f4 = 0.0f; }
    } else {
        // overflow fallback (statistically never): first 32 matches scanning ascending j
        // are exactly the 32 smallest original indices, already in order.
        n = MAXP;
        slot = lane;
        if (lane == 0) {
            int m = 0;
            for (int j = 0; j < N_POINTS && m < MAXP; j++) {
                const float* p = pts + (size_t)j * NFEAT;
                int cx = (int)floorf((p[0] + 50.0f) * 4.0f);
                int cy = (int)floorf((p[1] + 50.0f) * 4.0f);
                int cz = (int)floorf((p[2] + 5.0f) * 0.125f);
                if (cx >= 0 && cx < GXD && cy >= 0 && cy < GYD && cz == 0 &&
                    cy * GXD + cx == cell) sidx[w][m++] = j;
            }
        }
        __syncwarp();
        int idx = sidx[w][lane];
        const float* p = pts + (size_t)idx * NFEAT;
        f0 = p[0]; f1 = p[1]; f2 = p[2]; f3 = p[3]; f4 = p[4];
    }

    // stage ranked points in smem (stride 5 is coprime to 32 -> conflict-free),
    // then write the 640B voxel row coalesced with streaming stores.
    float* sb = sbuf[w];
    float* d = sb + slot * NFEAT;
    d[0] = f0; d[1] = f1; d[2] = f2; d[3] = f3; d[4] = f4;
    __syncwarp();
    float4* s4 = (float4*)sb;
    float4* dst = (float4*)(out + (size_t)gw * (MAXP * NFEAT));
    #pragma unroll
    for (int j = lane; j < 40; j += 32) __stcs(&dst[j], s4[j]);
    if (lane == 0) {
        int cy = cell / GXD, cx = cell - cy * GXD;
        float* oc = out + OUT_COORD_OFF + (size_t)gw * 3;
        __stcs(&oc[0], 0.0f);           // z
        __stcs(&oc[1], (float)cy);      // y
        __stcs(&oc[2], (float)cx);      // x
        __stcs(&out[OUT_NUM_OFF + gw], (float)n);
    }
}

extern "C" void kernel_launch(void* const* d_in, const int* in_sizes, int n_in,
                              void* d_out, int out_size) {
    const float* pts = (const float*)d_in[0];
    float* out = (float*)d_out;
    (void)in_sizes; (void)n_in; (void)out_size;

    k_assign<<<(N_POINTS / PPT + 255) / 256, 256>>>((const float4*)pts);
    k_scan  <<<SCAN_BLOCKS, 1024>>>();
    k_emit  <<<(MAXV * 32) / 256, 256>>>(pts, out);
}

// round 11
// speedup vs baseline: 1.4940x; 1.4940x over previous
#include <cuda_runtime.h>
#include <stdint.h>

#define N_POINTS 1200000
#define NFEAT 5
#define GXD 400
#define GYD 400
#define NCELLS (GXD*GYD)          // 160000
#define NCELLS_PAD 163840         // 40 * 4096
#define MAXV 60000
#define MAXP 32
#define OUT_COORD_OFF (MAXV*MAXP*NFEAT)        // 9,600,000
#define OUT_NUM_OFF   (OUT_COORD_OFF + MAXV*3) // 9,780,000
#define SCAN_BLOCKS 40
#define CELLS_PER_BLOCK 4096       // 1024 threads * 4 cells
#define DYN_TOTAL (NCELLS_PAD + SCAN_BLOCKS)
#define PPT 8                      // points per thread in assign

// [0,NCELLS_PAD) = per-cell counts, then SCAN_BLOCKS lookback states.
// Zero-initialized at load; k_emit re-zeroes it each launch for the next replay.
__device__ unsigned g_dyn[DYN_TOTAL];
__device__ int      g_totvox;
__device__ unsigned g_voxlist[MAXV];            // cell(18b) | min(cnt,16383)<<18
// slotA[cell][rank] = {x,y,z,idx_bits}: 16B scattered store = SAME sector/wavefront
// count as the old 4B index store, but saves emit its main gather load.
__device__ float4   g_slotA[(size_t)NCELLS * MAXP];

__device__ __forceinline__ void do_point(int idx, float x, float y, float z) {
    // exact: (v+50)*4 == (v-(-50))/0.25 ; (v+5)*0.125 == (v-(-5))/8
    int cx = (int)floorf((x + 50.0f) * 4.0f);
    int cy = (int)floorf((y + 50.0f) * 4.0f);
    int cz = (int)floorf((z + 5.0f) * 0.125f);
    if (cx >= 0 && cx < GXD && cy >= 0 && cy < GYD && cz == 0) {
        int cell = cy * GXD + cx;
        unsigned r = atomicAdd(&g_dyn[cell], 1u);
        if (r < MAXP)
            g_slotA[(size_t)cell * MAXP + r] = make_float4(x, y, z, __int_as_float(idx));
    }
}

// ---------------- assign: 8 points/thread, single 16B scattered store per point ----------------
__global__ void __launch_bounds__(256) k_assign(const float4* __restrict__ pts4) {
    int t = blockIdx.x * blockDim.x + threadIdx.x;
    if (t >= N_POINTS / PPT) return;
    // 8 points = 160 bytes = 10 aligned float4 loads, all independent
    const float4* src = pts4 + (size_t)t * 10;
    float4 q0 = src[0], q1 = src[1], q2 = src[2], q3 = src[3], q4 = src[4];
    float4 q5 = src[5], q6 = src[6], q7 = src[7], q8 = src[8], q9 = src[9];
    int base = t * PPT;
    // point k = floats [5k,5k+5) across q0..q9; only xyz needed here
    do_point(base + 0, q0.x, q0.y, q0.z);
    do_point(base + 1, q1.y, q1.z, q1.w);
    do_point(base + 2, q2.z, q2.w, q3.x);
    do_point(base + 3, q3.w, q4.x, q4.y);
    do_point(base + 4, q5.x, q5.y, q5.z);
    do_point(base + 5, q6.y, q6.z, q6.w);
    do_point(base + 6, q7.z, q7.w, q8.x);
    do_point(base + 7, q8.w, q9.x, q9.y);
}

// ---------------- scan: single-wave decoupled lookback + voxel-list compaction ----------------
__global__ void __launch_bounds__(1024, 1) k_scan() {
    __shared__ int wsum[32];
    __shared__ unsigned s_prefix;
    unsigned* state = g_dyn + NCELLS_PAD;
    const int t = threadIdx.x, b = blockIdx.x;
    const int lane = t & 31, w = t >> 5;
    const int c0 = b * CELLS_PER_BLOCK + t * 4;

    uint4 c4 = *(const uint4*)&g_dyn[c0];
    int o0 = c4.x ? 1 : 0, o1 = c4.y ? 1 : 0, o2 = c4.z ? 1 : 0, o3 = c4.w ? 1 : 0;
    int s = o0 + o1 + o2 + o3;

    int x = s;
    #pragma unroll
    for (int o = 1; o < 32; o <<= 1) {
        int v = __shfl_up_sync(0xffffffffu, x, o);
        if (lane >= o) x += v;
    }
    if (lane == 31) wsum[w] = x;
    __syncthreads();
    if (w == 0) {
        int y = wsum[lane];
        #pragma unroll
        for (int o = 1; o < 32; o <<= 1) {
            int v = __shfl_up_sync(0xffffffffu, y, o);
            if (lane >= o) y += v;
        }
        wsum[lane] = y;
    }
    __syncthreads();
    int incl = x + (w ? wsum[w - 1] : 0);
    unsigned agg = (unsigned)wsum[31];

    if (t == 0) {
        if (b == 0) atomicExch(&state[0], (2u << 30) | agg);
        else        atomicExch(&state[b], (1u << 30) | agg);
    }
    if (w == 0) {
        if (b == 0) { if (lane == 0) s_prefix = 0; }
        else {
            unsigned run = 0;
            int j = b - 1 - lane;
            for (;;) {
                unsigned sv = (j >= 0) ? *(volatile unsigned*)&state[j] : (2u << 30);
                unsigned flag = sv >> 30;
                if (__all_sync(0xffffffffu, flag != 0u)) {
                    unsigned pm = __ballot_sync(0xffffffffu, flag >= 2u);
                    int fp = (pm != 0u) ? (__ffs(pm) - 1) : -1;
                    unsigned contrib = (fp < 0 || lane <= fp) ? (sv & 0x3FFFFFFFu) : 0u;
                    #pragma unroll
                    for (int o = 16; o; o >>= 1)
                        contrib += __shfl_down_sync(0xffffffffu, contrib, o);
                    contrib = __shfl_sync(0xffffffffu, contrib, 0);
                    run += contrib;
                    if (fp >= 0) break;
                    j -= 32;
                }
            }
            if (lane == 0) {
                s_prefix = run;
                atomicExch(&state[b], (2u << 30) | (run + agg));
            }
        }
    }
    __syncthreads();

    int e = (int)s_prefix + incl - s;   // exclusive prefix of occupancy before cell c0
    if (o0) { if (e < MAXV) g_voxlist[e] = (unsigned)(c0+0) | (umin(c4.x, 16383u) << 18); e++; }
    if (o1) { if (e < MAXV) g_voxlist[e] = (unsigned)(c0+1) | (umin(c4.y, 16383u) << 18); e++; }
    if (o2) { if (e < MAXV) g_voxlist[e] = (unsigned)(c0+2) | (umin(c4.z, 16383u) << 18); e++; }
    if (o3) { if (e < MAXV) g_voxlist[e] = (unsigned)(c0+3) | (umin(c4.w, 16383u) << 18); e++; }
    if (b == SCAN_BLOCKS - 1 && t == 1023) g_totvox = e;
}

// ---------------- emit: coalesced slot read + small f3/f4 gather ----------------
__global__ void __launch_bounds__(256) k_emit(const float* __restrict__ pts,
                                              float* __restrict__ out) {
    int gid  = blockIdx.x * blockDim.x + threadIdx.x;
    int gw   = gid >> 5;                  // voxel index
    int lane = threadIdx.x & 31;
    int w    = (threadIdx.x >> 5) & 7;
    __shared__ float sbuf[8][160];
    __shared__ int   sidx[8][32];

    // reset counters + lookback state for the next replay (globals start zeroed at load)
    if (gid < DYN_TOTAL) g_dyn[gid] = 0;

    if (gw >= MAXV) return;
    int tv = g_totvox;
    if (gw >= tv) {
        // zero-fill unowned voxel (no-op when totvox >= MAXV)
        float4 z = make_float4(0.f, 0.f, 0.f, 0.f);
        float4* dst = (float4*)(out + (size_t)gw * (MAXP * NFEAT));
        for (int j = lane; j < 40; j += 32) __stcs(&dst[j], z);
        if (lane == 0) {
            float* oc = out + OUT_COORD_OFF + (size_t)gw * 3;
            __stcs(&oc[0], 0.f); __stcs(&oc[1], 0.f); __stcs(&oc[2], 0.f);
            __stcs(&out[OUT_NUM_OFF + gw], 0.f);
        }
        return;
    }

    unsigned packed = __ldcs(&g_voxlist[gw]);
    int cell = (int)(packed & 0x3FFFFu);
    int cnt  = (int)(packed >> 18);
    float f0 = 0.f, f1 = 0.f, f2 = 0.f, f3 = 0.f, f4 = 0.f;
    int slot, n;

    if (cnt <= MAXP) {
        n = cnt;
        int idx = 0x7fffffff;
        if (lane < cnt) {
            // coalesced: warp reads contiguous 16B/lane (512B per warp)
            float4 a = __ldcs(&g_slotA[(size_t)cell * MAXP + lane]);
            idx = __float_as_int(a.w);
            f0 = a.x; f1 = a.y; f2 = a.z;
            // f3,f4 live at floats 5i+3, 5i+4. One aligned 16B word starting at
            // (5i+3)>>2 holds both unless (i+3)&3 == 3 (25%: f4 = next word's .x).
            const float4* p4 = (const float4*)pts;
            int w1 = (5 * idx + 3) >> 2;
            int o  = (idx + 3) & 3;
            float4 A = __ldg(&p4[w1]);
            f3 = o==0 ? A.x : o==1 ? A.y : o==2 ? A.z : A.w;
            if (o == 3) f4 = __ldg((const float*)&p4[w1 + 1]);
            else        f4 = o==0 ? A.y : o==1 ? A.z : A.w;
        }
        int rank = 0;
        #pragma unroll
        for (int k = 0; k < 32; k++) {
            int o = __shfl_sync(0xffffffffu, idx, k);
            rank += (o < idx) ? 1 : 0;
        }
        slot = (lane < cnt) ? rank : lane;   // ranks tile [0,cnt), idle lanes tile [cnt,32)
    } else {
        // overflow fallback (statistically never): first 32 matches scanning ascending j
        // are exactly the 32 smallest original indices, already in order.
        n = MAXP;
        slot = lane;
        if (lane == 0) {
            int m = 0;
            for (int j = 0; j < N_POINTS && m < MAXP; j++) {
                const float* p = pts + (size_t)j * NFEAT;
                int cx = (int)floorf((p[0] + 50.0f) * 4.0f);
                int cy = (int)floorf((p[1] + 50.0f) * 4.0f);
                int cz = (int)floorf((p[2] + 5.0f) * 0.125f);
                if (cx >= 0 && cx < GXD && cy >= 0 && cy < GYD && cz == 0 &&
                    cy * GXD + cx == cell) sidx[w][m++] = j;
            }
        }
        __syncwarp();
        int idx = sidx[w][lane];
        const float* p = pts + (size_t)idx * NFEAT;
        f0 = p[0]; f1 = p[1]; f2 = p[2]; f3 = p[3]; f4 = p[4];
    }

    // stage ranked points in smem (stride 5 is coprime to 32 -> conflict-free),
    // then write the 640B voxel row coalesced with streaming stores.
    float* sb = sbuf[w];
    float* d = sb + slot * NFEAT;
    d[0] = f0; d[1] = f1; d[2] = f2; d[3] = f3; d[4] = f4;
    __syncwarp();
    float4* s4 = (float4*)sb;
    float4* dst = (float4*)(out + (size_t)gw * (MAXP * NFEAT));
    #pragma unroll
    for (int j = lane; j < 40; j += 32) __stcs(&dst[j], s4[j]);
    if (lane == 0) {
        int cy = cell / GXD, cx = cell - cy * GXD;
        float* oc = out + OUT_COORD_OFF + (size_t)gw * 3;
        __stcs(&oc[0], 0.0f);           // z
        __stcs(&oc[1], (float)cy);      // y
        __stcs(&oc[2], (float)cx);      // x
        __stcs(&out[OUT_NUM_OFF + gw], (float)n);
    }
}

extern "C" void kernel_launch(void* const* d_in, const int* in_sizes, int n_in,
                              void* d_out, int out_size) {
    const float* pts = (const float*)d_in[0];
    float* out = (float*)d_out;
    (void)in_sizes; (void)n_in; (void)out_size;

    k_assign<<<(N_POINTS / PPT + 255) / 256, 256>>>((const float4*)pts);
    k_scan  <<<SCAN_BLOCKS, 1024>>>();
    k_emit  <<<(MAXV * 32) / 256, 256>>>(pts, out);
}

// round 12
// speedup vs baseline: 1.4953x; 1.0009x over previous
#include <cuda_runtime.h>
#include <stdint.h>

#define N_POINTS 1200000
#define NFEAT 5
#define GXD 400
#define GYD 400
#define NCELLS (GXD*GYD)          // 160000
#define NCELLS_PAD 163840         // 40 * 4096
#define MAXV 60000
#define MAXP 32
#define OUT_COORD_OFF (MAXV*MAXP*NFEAT)        // 9,600,000
#define OUT_NUM_OFF   (OUT_COORD_OFF + MAXV*3) // 9,780,000
#define SCAN_BLOCKS 40
#define CELLS_PER_BLOCK 4096       // 1024 threads * 4 cells
#define DYN_TOTAL (NCELLS_PAD + SCAN_BLOCKS)
#define PPT 4                      // points per thread in assign

// [0,NCELLS_PAD) = per-cell counts, then SCAN_BLOCKS lookback states.
// Zero-initialized at load; k_emit re-zeroes it each launch for the next replay.
__device__ unsigned g_dyn[DYN_TOTAL];
__device__ int      g_totvox;
__device__ unsigned g_voxlist[MAXV];            // cell(18b) | min(cnt,16383)<<18
// slotA[cell][rank] = {x,y,z,idx_bits}: 16B scattered store (one sector per point,
// same wavefront count as a 4B store) — emit only needs to gather f3,f4.
__device__ float4   g_slotA[(size_t)NCELLS * MAXP];

__device__ __forceinline__ void do_point(int idx, float x, float y, float z) {
    // exact: (v+50)*4 == (v-(-50))/0.25 ; (v+5)*0.125 == (v-(-5))/8
    int cx = (int)floorf((x + 50.0f) * 4.0f);
    int cy = (int)floorf((y + 50.0f) * 4.0f);
    int cz = (int)floorf((z + 5.0f) * 0.125f);
    if (cx >= 0 && cx < GXD && cy >= 0 && cy < GYD && cz == 0) {
        int cell = cy * GXD + cx;
        unsigned r = atomicAdd(&g_dyn[cell], 1u);
        if (r < MAXP)
            g_slotA[(size_t)cell * MAXP + r] = make_float4(x, y, z, __int_as_float(idx));
    }
}

// ---------------- assign: 4 points/thread, 2x grid for latency hiding ----------------
__global__ void __launch_bounds__(256) k_assign(const float4* __restrict__ pts4) {
    int t = blockIdx.x * blockDim.x + threadIdx.x;
    if (t >= N_POINTS / PPT) return;
    // 4 points = 80 bytes = 5 aligned float4 loads, all independent
    const float4* src = pts4 + (size_t)t * 5;
    float4 q0 = src[0], q1 = src[1], q2 = src[2], q3 = src[3], q4 = src[4];
    int base = t * PPT;
    // point k = floats [5k,5k+5) across q0..q4; only xyz needed here
    do_point(base + 0, q0.x, q0.y, q0.z);
    do_point(base + 1, q1.y, q1.z, q1.w);
    do_point(base + 2, q2.z, q2.w, q3.x);
    do_point(base + 3, q3.w, q4.x, q4.y);
}

// ---------------- scan: single-wave decoupled lookback + voxel-list compaction ----------------
__global__ void __launch_bounds__(1024, 1) k_scan() {
    __shared__ int wsum[32];
    __shared__ unsigned s_prefix;
    unsigned* state = g_dyn + NCELLS_PAD;
    const int t = threadIdx.x, b = blockIdx.x;
    const int lane = t & 31, w = t >> 5;
    const int c0 = b * CELLS_PER_BLOCK + t * 4;

    uint4 c4 = *(const uint4*)&g_dyn[c0];
    int o0 = c4.x ? 1 : 0, o1 = c4.y ? 1 : 0, o2 = c4.z ? 1 : 0, o3 = c4.w ? 1 : 0;
    int s = o0 + o1 + o2 + o3;

    int x = s;
    #pragma unroll
    for (int o = 1; o < 32; o <<= 1) {
        int v = __shfl_up_sync(0xffffffffu, x, o);
        if (lane >= o) x += v;
    }
    if (lane == 31) wsum[w] = x;
    __syncthreads();
    if (w == 0) {
        int y = wsum[lane];
        #pragma unroll
        for (int o = 1; o < 32; o <<= 1) {
            int v = __shfl_up_sync(0xffffffffu, y, o);
            if (lane >= o) y += v;
        }
        wsum[lane] = y;
    }
    __syncthreads();
    int incl = x + (w ? wsum[w - 1] : 0);
    unsigned agg = (unsigned)wsum[31];

    if (t == 0) {
        if (b == 0) atomicExch(&state[0], (2u << 30) | agg);
        else        atomicExch(&state[b], (1u << 30) | agg);
    }
    if (w == 0) {
        if (b == 0) { if (lane == 0) s_prefix = 0; }
        else {
            unsigned run = 0;
            int j = b - 1 - lane;
            for (;;) {
                unsigned sv = (j >= 0) ? *(volatile unsigned*)&state[j] : (2u << 30);
                unsigned flag = sv >> 30;
                if (__all_sync(0xffffffffu, flag != 0u)) {
                    unsigned pm = __ballot_sync(0xffffffffu, flag >= 2u);
                    int fp = (pm != 0u) ? (__ffs(pm) - 1) : -1;
                    unsigned contrib = (fp < 0 || lane <= fp) ? (sv & 0x3FFFFFFFu) : 0u;
                    #pragma unroll
                    for (int o = 16; o; o >>= 1)
                        contrib += __shfl_down_sync(0xffffffffu, contrib, o);
                    contrib = __shfl_sync(0xffffffffu, contrib, 0);
                    run += contrib;
                    if (fp >= 0) break;
                    j -= 32;
                }
            }
            if (lane == 0) {
                s_prefix = run;
                atomicExch(&state[b], (2u << 30) | (run + agg));
            }
        }
    }
    __syncthreads();

    int e = (int)s_prefix + incl - s;   // exclusive prefix of occupancy before cell c0
    if (o0) { if (e < MAXV) g_voxlist[e] = (unsigned)(c0+0) | (umin(c4.x, 16383u) << 18); e++; }
    if (o1) { if (e < MAXV) g_voxlist[e] = (unsigned)(c0+1) | (umin(c4.y, 16383u) << 18); e++; }
    if (o2) { if (e < MAXV) g_voxlist[e] = (unsigned)(c0+2) | (umin(c4.z, 16383u) << 18); e++; }
    if (o3) { if (e < MAXV) g_voxlist[e] = (unsigned)(c0+3) | (umin(c4.w, 16383u) << 18); e++; }
    if (b == SCAN_BLOCKS - 1 && t == 1023) g_totvox = e;
}

// ---------------- emit: coalesced slot read + small f3/f4 gather ----------------
__global__ void __launch_bounds__(256) k_emit(const float* __restrict__ pts,
                                              float* __restrict__ out) {
    int gid  = blockIdx.x * blockDim.x + threadIdx.x;
    int gw   = gid >> 5;                  // voxel index
    int lane = threadIdx.x & 31;
    int w    = (threadIdx.x >> 5) & 7;
    __shared__ float sbuf[8][160];
    __shared__ int   sidx[8][32];

    // reset counters + lookback state for the next replay (globals start zeroed at load)
    if (gid < DYN_TOTAL) g_dyn[gid] = 0;

    if (gw >= MAXV) return;
    int tv = g_totvox;
    if (gw >= tv) {
        // zero-fill unowned voxel (no-op when totvox >= MAXV)
        float4 z = make_float4(0.f, 0.f, 0.f, 0.f);
        float4* dst = (float4*)(out + (size_t)gw * (MAXP * NFEAT));
        for (int j = lane; j < 40; j += 32) __stcs(&dst[j], z);
        if (lane == 0) {
            float* oc = out + OUT_COORD_OFF + (size_t)gw * 3;
            __stcs(&oc[0], 0.f); __stcs(&oc[1], 0.f); __stcs(&oc[2], 0.f);
            __stcs(&out[OUT_NUM_OFF + gw], 0.f);
        }
        return;
    }

    unsigned packed = __ldcs(&g_voxlist[gw]);
    int cell = (int)(packed & 0x3FFFFu);
    int cnt  = (int)(packed >> 18);
    float f0 = 0.f, f1 = 0.f, f2 = 0.f, f3 = 0.f, f4 = 0.f;
    int slot, n;

    if (cnt <= MAXP) {
        n = cnt;
        int idx = 0x7fffffff;
        if (lane < cnt) {
            // coalesced: warp reads contiguous 16B/lane (512B per warp)
            float4 a = __ldcs(&g_slotA[(size_t)cell * MAXP + lane]);
            idx = __float_as_int(a.w);
            f0 = a.x; f1 = a.y; f2 = a.z;
            // f3,f4 live at floats 5i+3, 5i+4. One aligned 16B word starting at
            // (5i+3)>>2 holds both unless (i+3)&3 == 3 (25%: f4 = next word's .x).
            const float4* p4 = (const float4*)pts;
            int w1 = (5 * idx + 3) >> 2;
            int o  = (idx + 3) & 3;
            float4 A = __ldg(&p4[w1]);
            f3 = o==0 ? A.x : o==1 ? A.y : o==2 ? A.z : A.w;
            if (o == 3) f4 = __ldg((const float*)&p4[w1 + 1]);
            else        f4 = o==0 ? A.y : o==1 ? A.z : A.w;
        }
        int rank = 0;
        #pragma unroll
        for (int k = 0; k < 32; k++) {
            int o = __shfl_sync(0xffffffffu, idx, k);
            rank += (o < idx) ? 1 : 0;
        }
        slot = (lane < cnt) ? rank : lane;   // ranks tile [0,cnt), idle lanes tile [cnt,32)
    } else {
        // overflow fallback (statistically never): first 32 matches scanning ascending j
        // are exactly the 32 smallest original indices, already in order.
        n = MAXP;
        slot = lane;
        if (lane == 0) {
            int m = 0;
            for (int j = 0; j < N_POINTS && m < MAXP; j++) {
                const float* p = pts + (size_t)j * NFEAT;
                int cx = (int)floorf((p[0] + 50.0f) * 4.0f);
                int cy = (int)floorf((p[1] + 50.0f) * 4.0f);
                int cz = (int)floorf((p[2] + 5.0f) * 0.125f);
                if (cx >= 0 && cx < GXD && cy >= 0 && cy < GYD && cz == 0 &&
                    cy * GXD + cx == cell) sidx[w][m++] = j;
            }
        }
        __syncwarp();
        int idx = sidx[w][lane];
        const float* p = pts + (size_t)idx * NFEAT;
        f0 = p[0]; f1 = p[1]; f2 = p[2]; f3 = p[3]; f4 = p[4];
    }

    // stage ranked points in smem (stride 5 is coprime to 32 -> conflict-free),
    // then write the 640B voxel row coalesced with streaming stores.
    float* sb = sbuf[w];
    float* d = sb + slot * NFEAT;
    d[0] = f0; d[1] = f1; d[2] = f2; d[3] = f3; d[4] = f4;
    __syncwarp();
    float4* s4 = (float4*)sb;
    float4* dst = (float4*)(out + (size_t)gw * (MAXP * NFEAT));
    #pragma unroll
    for (int j = lane; j < 40; j += 32) __stcs(&dst[j], s4[j]);
    if (lane == 0) {
        int cy = cell / GXD, cx = cell - cy * GXD;
        float* oc = out + OUT_COORD_OFF + (size_t)gw * 3;
        __stcs(&oc[0], 0.0f);           // z
        __stcs(&oc[1], (float)cy);      // y
        __stcs(&oc[2], (float)cx);      // x
        __stcs(&out[OUT_NUM_OFF + gw], (float)n);
    }
}

extern "C" void kernel_launch(void* const* d_in, const int* in_sizes, int n_in,
                              void* d_out, int out_size) {
    const float* pts = (const float*)d_in[0];
    float* out = (float*)d_out;
    (void)in_sizes; (void)n_in; (void)out_size;

    k_assign<<<(N_POINTS / PPT + 255) / 256, 256>>>((const float4*)pts);
    k_scan  <<<SCAN_BLOCKS, 1024>>>();
    k_emit  <<<(MAXV * 32) / 256, 256>>>(pts, out);
}